// round 7
// baseline (speedup 1.0000x reference)
#include <cuda_runtime.h>
#include <cuda_fp16.h>
#include <cstdint>

#define NN 2048
#define DD 512
#define KPC 8
#define TM 128
#define TN 64
#define KS 64
#define NSLAB (DD / KS)

// ---------------- scratch (no allocations allowed) ----------------
__device__ __half g_xf[NN * DD];             // fp16 normalized (MMA operand)
__device__ float g_sq[NN];
__device__ float g_pos[NN * 8];              // P_k = exp(pos dist), self slot = 0
__device__ float g_row[NN * 4];              // cnt, trip_sum, pos_sum, neg_sum
__device__ int g_done;

// ---------------- helpers ----------------
__device__ __forceinline__ uint32_t smem_to_u32(const void* p) {
    uint32_t a;
    asm("{ .reg .u64 t; cvta.to.shared.u64 t, %1; cvt.u32.u64 %0, t; }" : "=r"(a) : "l"(p));
    return a;
}
__device__ __forceinline__ float fast_exp2(float x) { float y; asm("ex2.approx.f32 %0, %1;" : "=f"(y) : "f"(x)); return y; }
__device__ __forceinline__ float fast_log2(float x) { float y; asm("lg2.approx.f32 %0, %1;" : "=f"(y) : "f"(x)); return y; }
__device__ __forceinline__ float warp_sum(float v) {
    #pragma unroll
    for (int o = 16; o; o >>= 1) v += __shfl_xor_sync(0xffffffffu, v, o);
    return v;
}

#define CPA(dst, src) \
    asm volatile("cp.async.cg.shared.global [%0], [%1], 16;" :: "r"(dst), "l"(src))
#define CPA_COMMIT() asm volatile("cp.async.commit_group;" ::: "memory")

__device__ __forceinline__ void ldm_x4(uint32_t* r, uint32_t addr) {
    asm volatile("ldmatrix.sync.aligned.m8n8.x4.shared.b16 {%0,%1,%2,%3}, [%4];"
                 : "=r"(r[0]), "=r"(r[1]), "=r"(r[2]), "=r"(r[3]) : "r"(addr));
}
__device__ __forceinline__ void mma_fp16(float* c, const uint32_t* a, uint32_t b0, uint32_t b1) {
    asm volatile(
        "mma.sync.aligned.m16n8k16.row.col.f32.f16.f16.f32 "
        "{%0,%1,%2,%3}, {%4,%5,%6,%7}, {%8,%9}, {%0,%1,%2,%3};"
        : "+f"(c[0]), "+f"(c[1]), "+f"(c[2]), "+f"(c[3])
        : "r"(a[0]), "r"(a[1]), "r"(a[2]), "r"(a[3]), "r"(b0), "r"(b1));
}

// ---------------------------------------------------------------------------
// 1) prep: per-class (8 rows): normalize, write fp16 + sq, 8x8 intra-class
//    dists -> P=exp(p) (self=0), init g_row.
// ---------------------------------------------------------------------------
#define XPAD 4
__global__ __launch_bounds__(256) void prep_kernel(const float* __restrict__ in) {
    __shared__ float xs[KPC][DD + XPAD];
    __shared__ float ssq[KPC];
    const int cls = blockIdx.x;
    const int tid = threadIdx.x;
    const int w = tid >> 5;
    const int l = tid & 31;
    const int row = cls * KPC + w;
    if (cls == 0 && tid == 0) g_done = 0;

    float4 v[4];
    const float4* src = reinterpret_cast<const float4*>(in + row * DD) + l * 4;
    #pragma unroll
    for (int q = 0; q < 4; q++) v[q] = src[q];
    float ss = 0.0f;
    #pragma unroll
    for (int q = 0; q < 4; q++)
        ss += v[q].x * v[q].x + v[q].y * v[q].y + v[q].z * v[q].z + v[q].w * v[q].w;
    ss = warp_sum(ss);
    float s = 4.0f * rsqrtf(ss);

    __half2* pf = reinterpret_cast<__half2*>(g_xf + row * DD + l * 16);
    #pragma unroll
    for (int q = 0; q < 4; q++) {
        float4 o4 = make_float4(v[q].x * s, v[q].y * s, v[q].z * s, v[q].w * s);
        xs[w][l * 16 + q * 4 + 0] = o4.x;
        xs[w][l * 16 + q * 4 + 1] = o4.y;
        xs[w][l * 16 + q * 4 + 2] = o4.z;
        xs[w][l * 16 + q * 4 + 3] = o4.w;
        pf[q * 2 + 0] = __half2(__float2half_rn(o4.x), __float2half_rn(o4.y));
        pf[q * 2 + 1] = __half2(__float2half_rn(o4.z), __float2half_rn(o4.w));
    }
    if (l == 0) { g_sq[row] = ss * s * s; ssq[w] = ss * s * s; }
    __syncthreads();

    if (tid < 64) {
        const float L2E = 1.4426950408889634f;
        int a = tid >> 3, b = tid & 7;
        float dot = 0.0f;
        #pragma unroll 4
        for (int q = 0; q < DD; q += 4) {
            dot += xs[a][q + 0] * xs[b][q + 0] + xs[a][q + 1] * xs[b][q + 1]
                 + xs[a][q + 2] * xs[b][q + 2] + xs[a][q + 3] * xs[b][q + 3];
        }
        int ia = cls * KPC + a;
        float p = ssq[a] + ssq[b] - 2.0f * dot;
        bool self = (a == b);
        g_pos[ia * 8 + b] = self ? 0.0f : fast_exp2(p * L2E);
        float ps = self ? 0.0f : p;
        ps += __shfl_xor_sync(0xffffffffu, ps, 1);
        ps += __shfl_xor_sync(0xffffffffu, ps, 2);
        ps += __shfl_xor_sync(0xffffffffu, ps, 4);
        if (b == 0) {
            g_row[ia * 4 + 0] = 0.0f;
            g_row[ia * 4 + 1] = 0.0f;
            g_row[ia * 4 + 2] = ps;
            g_row[ia * 4 + 3] = 0.0f;
        }
    }
}

// ---------------------------------------------------------------------------
// 2) fused HMMA Gram (128x64 tile, 512 CTAs, 3 CTAs/SM) + epilogue + finalize
// ---------------------------------------------------------------------------
#define SM_SQI 0
#define SM_SQJ 512
#define SM_PI  1024
#define SM_BUF 6144
#define A_OFF 0
#define B_OFF 16384
#define BUFSZ 24576
#define SMEM_TOTAL (SM_BUF + 2 * BUFSZ)

__device__ __forceinline__ void load_slab_async(uint32_t smb, int buf, int s,
                                                int bi, int bj, int tid) {
    const int k0 = s * KS;
    const uint32_t bufb = smb + SM_BUF + buf * BUFSZ;
    // A: 128 rows x 8 chunks of 16B; 2 threads per row
    {
        const int row = tid >> 1;
        const int cb = (tid & 1) * 4;
        const char* sp = reinterpret_cast<const char*>(g_xf + (bi + row) * DD + k0);
        uint32_t dA = bufb + A_OFF + row * 128;
        #pragma unroll
        for (int c = 0; c < 4; c++) {
            int ch = cb + c;
            CPA(dA + (((ch ^ (row & 7))) << 4), sp + ch * 16);
        }
    }
    // B: 64 rows x 8 chunks; 4 threads per row
    {
        const int row = tid >> 2;
        const int cb = (tid & 3) * 2;
        const char* sp = reinterpret_cast<const char*>(g_xf + (bj + row) * DD + k0);
        uint32_t dB = bufb + B_OFF + row * 128;
        #pragma unroll
        for (int c = 0; c < 2; c++) {
            int ch = cb + c;
            CPA(dB + (((ch ^ (row & 7))) << 4), sp + ch * 16);
        }
    }
}

__global__ __launch_bounds__(256, 3) void fused_kernel(float* __restrict__ out, int out_size) {
    extern __shared__ char smem[];
    const int tid = threadIdx.x;
    const int wid = tid >> 5;
    const int lane = tid & 31;
    const int bi = blockIdx.y * TM;
    const int bj = blockIdx.x * TN;
    const int mloc = (wid >> 1) * 32;    // 4 m-warps of 32 rows
    const int nloc = (wid & 1) * 32;     // 2 n-warps of 32 cols
    const uint32_t smb = smem_to_u32(smem);
    float* sSqi = reinterpret_cast<float*>(smem + SM_SQI);
    float* sSqj = reinterpret_cast<float*>(smem + SM_SQJ);
    float* sPi  = reinterpret_cast<float*>(smem + SM_PI);

    load_slab_async(smb, 0, 0, bi, bj, tid);
    CPA_COMMIT();

    if (tid < 128) sSqi[tid] = g_sq[bi + tid];
    else if (tid < 192) sSqj[tid - 128] = g_sq[bj + (tid - 128)];
    reinterpret_cast<float4*>(sPi)[tid] = reinterpret_cast<const float4*>(g_pos + bi * 8)[tid];

    float acc[2][4][4];
    #pragma unroll
    for (int mi = 0; mi < 2; mi++)
        #pragma unroll
        for (int ni = 0; ni < 4; ni++)
            #pragma unroll
            for (int r = 0; r < 4; r++) acc[mi][ni][r] = 0.0f;

    const int rA = (lane & 7) + (((lane >> 3) & 1) << 3);
    const int cSel = lane >> 4;
    const int x7 = lane & 7;

    #pragma unroll 1
    for (int s = 0; s < NSLAB; s++) {
        const int b = s & 1;
        if (s + 1 < NSLAB) { load_slab_async(smb, 1 - b, s + 1, bi, bj, tid); CPA_COMMIT(); }
        if (s + 1 < NSLAB) asm volatile("cp.async.wait_group 1;" ::: "memory");
        else               asm volatile("cp.async.wait_group 0;" ::: "memory");
        __syncthreads();

        const uint32_t base = smb + SM_BUF + b * BUFSZ;
        #pragma unroll
        for (int ks = 0; ks < 4; ks++) {
            uint32_t af[2][4];
            #pragma unroll
            for (int mi = 0; mi < 2; mi++) {
                int row = mloc + mi * 16 + rA;
                uint32_t ad = base + A_OFF + row * 128 + ((((2 * ks + cSel) ^ x7)) << 4);
                ldm_x4(af[mi], ad);
            }
            uint32_t bfr[2][4];
            #pragma unroll
            for (int nt = 0; nt < 2; nt++) {
                int row = nloc + nt * 16 + rA;
                uint32_t bd = base + B_OFF + row * 128 + ((((2 * ks + cSel) ^ x7)) << 4);
                ldm_x4(bfr[nt], bd);
            }
            #pragma unroll
            for (int mi = 0; mi < 2; mi++)
                #pragma unroll
                for (int nt = 0; nt < 2; nt++) {
                    mma_fp16(acc[mi][2 * nt],     af[mi], bfr[nt][0], bfr[nt][2]);
                    mma_fp16(acc[mi][2 * nt + 1], af[mi], bfr[nt][1], bfr[nt][3]);
                }
        }
        __syncthreads();
    }

    // ---- triplet epilogue on register accumulators ----
    const float L2E = 1.4426950408889634f;
    const float LN2 = 0.6931471805599453f;
    const float TH  = 1.99970566f;            // 1 + (exp(0.693f)-1)

    #pragma unroll
    for (int mi = 0; mi < 2; mi++) {
        #pragma unroll
        for (int h = 0; h < 2; h++) {
            const int rl = mloc + mi * 16 + h * 8 + (lane >> 2);
            const int gi = bi + rl;
            const float sqi = sSqi[rl];
            const float4 p0 = *reinterpret_cast<const float4*>(sPi + rl * 8);
            const float4 p1 = *reinterpret_cast<const float4*>(sPi + rl * 8 + 4);
            float cnt = 0.0f, trip = 0.0f, neg = 0.0f;
            #pragma unroll
            for (int ni = 0; ni < 4; ni++) {
                #pragma unroll
                for (int rr = 0; rr < 2; rr++) {
                    const int cl = nloc + ni * 8 + (lane & 3) * 2 + rr;
                    const float d = sqi + sSqj[cl] - 2.0f * acc[mi][ni][h * 2 + rr];
                    const int gj = bj + cl;
                    if ((gi >> 3) != (gj >> 3)) {
                        neg += d;
                        float en = fast_exp2(-d * L2E);
                        float f0 = fmaf(p0.x, en, 1.0f);
                        float f1 = fmaf(p0.y, en, 1.0f);
                        float f2 = fmaf(p0.z, en, 1.0f);
                        float f3 = fmaf(p0.w, en, 1.0f);
                        float f4 = fmaf(p1.x, en, 1.0f);
                        float f5 = fmaf(p1.y, en, 1.0f);
                        float f6 = fmaf(p1.z, en, 1.0f);
                        float f7 = fmaf(p1.w, en, 1.0f);
                        cnt += (f0 > TH) ? 1.0f : 0.0f;
                        cnt += (f1 > TH) ? 1.0f : 0.0f;
                        cnt += (f2 > TH) ? 1.0f : 0.0f;
                        cnt += (f3 > TH) ? 1.0f : 0.0f;
                        cnt += (f4 > TH) ? 1.0f : 0.0f;
                        cnt += (f5 > TH) ? 1.0f : 0.0f;
                        cnt += (f6 > TH) ? 1.0f : 0.0f;
                        cnt += (f7 > TH) ? 1.0f : 0.0f;
                        float pa = ((f0 > TH) ? f0 : 1.0f);
                        pa *= ((f1 > TH) ? f1 : 1.0f);
                        pa *= ((f2 > TH) ? f2 : 1.0f);
                        pa *= ((f3 > TH) ? f3 : 1.0f);
                        float pb = ((f4 > TH) ? f4 : 1.0f);
                        pb *= ((f5 > TH) ? f5 : 1.0f);
                        pb *= ((f6 > TH) ? f6 : 1.0f);
                        pb *= ((f7 > TH) ? f7 : 1.0f);
                        trip += LN2 * (fast_log2(pa) + fast_log2(pb));
                    }
                }
            }
            cnt  += __shfl_xor_sync(0xffffffffu, cnt, 1);
            cnt  += __shfl_xor_sync(0xffffffffu, cnt, 2);
            trip += __shfl_xor_sync(0xffffffffu, trip, 1);
            trip += __shfl_xor_sync(0xffffffffu, trip, 2);
            neg  += __shfl_xor_sync(0xffffffffu, neg, 1);
            neg  += __shfl_xor_sync(0xffffffffu, neg, 2);
            if ((lane & 3) == 0) {
                atomicAdd(&g_row[gi * 4 + 0], cnt);
                atomicAdd(&g_row[gi * 4 + 1], trip);
                atomicAdd(&g_row[gi * 4 + 3], neg);
            }
        }
    }

    // ---- last-block finalize ----
    __syncthreads();
    __shared__ int slast;
    if (tid == 0) {
        __threadfence();
        int o = atomicAdd(&g_done, 1);
        slast = (o == (int)(gridDim.x * gridDim.y) - 1);
    }
    __syncthreads();
    if (!slast) return;
    __threadfence();

    double sm = 0, tc = 0, acd = 0, psd = 0, nsd = 0;
    for (int i = tid; i < NN; i += 256) {
        float4 r = *reinterpret_cast<const float4*>(g_row + i * 4);
        tc += (double)r.x; psd += (double)r.z; nsd += (double)r.w;
        if (r.x > 0.0f) sm += (double)(r.y / r.x);
        else            acd += 1.0;
    }
    #pragma unroll
    for (int o = 16; o; o >>= 1) {
        sm  += __shfl_xor_sync(0xffffffffu, sm, o);
        tc  += __shfl_xor_sync(0xffffffffu, tc, o);
        acd += __shfl_xor_sync(0xffffffffu, acd, o);
        psd += __shfl_xor_sync(0xffffffffu, psd, o);
        nsd += __shfl_xor_sync(0xffffffffu, nsd, o);
    }
    __shared__ double sh[5][8];
    int w = tid >> 5;
    if ((tid & 31) == 0) { sh[0][w] = sm; sh[1][w] = tc; sh[2][w] = acd; sh[3][w] = psd; sh[4][w] = nsd; }
    __syncthreads();
    if (tid == 0) {
        double Sm = 0, Tc = 0, Ac = 0, Ps = 0, Ns = 0;
        #pragma unroll
        for (int ww = 0; ww < 8; ww++) {
            Sm += sh[0][ww]; Tc += sh[1][ww]; Ac += sh[2][ww]; Ps += sh[3][ww]; Ns += sh[4][ww];
        }
        float loss = (Tc > 0.0) ? (float)(Sm / Tc) : 0.0f;
        if (out_size >= 1) out[0] = loss;
        if (out_size >= 2) out[1] = (float)(Ac / (double)NN);
        if (out_size >= 3) out[2] = (float)(Ps / ((double)NN * (KPC - 1)));
        if (out_size >= 4) out[3] = (float)(Ns / ((double)NN * (NN - KPC)));
    }
    for (int idx = 4 + tid; idx < out_size; idx += 256) out[idx] = 0.0f;
}

// ---------------------------------------------------------------------------
extern "C" void kernel_launch(void* const* d_in, const int* in_sizes, int n_in,
                              void* d_out, int out_size) {
    const float* inputs = (const float*)d_in[0];
    (void)in_sizes; (void)n_in;
    float* out = (float*)d_out;

    cudaFuncSetAttribute(fused_kernel, cudaFuncAttributeMaxDynamicSharedMemorySize, SMEM_TOTAL);

    prep_kernel<<<NN / KPC, 256>>>(inputs);
    fused_kernel<<<dim3(NN / TN, NN / TM), 256, SMEM_TOTAL>>>(out, out_size);
}